// round 6
// baseline (speedup 1.0000x reference)
#include <cuda_runtime.h>
#include <cstdint>
#include <cstring>

// ---------------------------------------------------------------------------
// MCNET binarized CNN (algebraic identities, see R0):
//   * sign(maxpool(hardtanh(v))) == sign(max(v))
//   * sign(hardtanh(int n)) == sign(n)
//   * L2..L4 activations are ternary {-1,0,+1} int8 sign maps
// R6 changes: l1 smem input tile + packed fma.rn.f32x2 (2 FMAs/inst),
// l3 smem-staged g_s2 tile + single pass over 8 oc, g_s3 as uint2 planes
// (8ch) so l4 loads halve.
// ---------------------------------------------------------------------------

static __device__ uint2 g_s1[32u * 256 * 256];         // [b,y,x, 8ch]  16.8 MB
static __device__ int4  g_s2[32u * 254 * 254];         // [b,y,x,16ch]  33.0 MB
static __device__ uint2 g_s3v[4][32u * 252 * 252];     // [og][b,y,x] 8ch/plane, 65 MB

static __device__ float g_w1f[216];    // [o=8][c=3][ky][kx] as float +-1/0
static __device__ int   g_w2p[288];    // [o=16][9 pos][2 packs of 4ch]
static __device__ int   g_w3p[1152];   // [o=32][9 pos][4 packs of 4ch]
static __device__ int   g_w4p[144];    // [o=2 ][9 pos][8 packs of 4ch]

__device__ __forceinline__ int sgnf(float v) { return (v > 0.f) - (v < 0.f); }
__device__ __forceinline__ int sgni(int v)   { return (v > 0) - (v < 0); }
__device__ __forceinline__ int pack4(int a, int b, int c, int d) {
    return (a & 0xFF) | ((b & 0xFF) << 8) | ((c & 0xFF) << 16) | ((d & 0xFF) << 24);
}

// ---- packed f32x2 helpers (Blackwell) -------------------------------------
__device__ __forceinline__ unsigned long long pk2(float lo, float hi) {
    unsigned long long r;
    asm("mov.b64 %0, {%1, %2};" : "=l"(r) : "f"(lo), "f"(hi));
    return r;
}
__device__ __forceinline__ void upk2(unsigned long long v, float& lo, float& hi) {
    asm("mov.b64 {%0, %1}, %2;" : "=f"(lo), "=f"(hi) : "l"(v));
}
__device__ __forceinline__ unsigned long long ffma2(unsigned long long a,
                                                    unsigned long long b,
                                                    unsigned long long c) {
    unsigned long long d;
    asm("fma.rn.f32x2 %0, %1, %2, %3;" : "=l"(d) : "l"(a), "l"(b), "l"(c));
    return d;
}

// ---------------------------------------------------------------------------
__global__ void prep_kernel(const float* __restrict__ w1, const float* __restrict__ w2,
                            const float* __restrict__ w3, const float* __restrict__ w4) {
    int t = threadIdx.x;
    for (int i = t; i < 216; i += blockDim.x) g_w1f[i] = (float)sgnf(w1[i]);
    for (int i = t; i < 288; i += blockDim.x) {
        int h = i & 1, pos = (i >> 1) % 9, o = i / 18;
        int ky = pos / 3, kx = pos % 3;
        int s[4];
        #pragma unroll
        for (int j = 0; j < 4; j++)
            s[j] = sgnf(w2[((o * 8 + (4 * h + j)) * 3 + ky) * 3 + kx]);
        g_w2p[i] = pack4(s[0], s[1], s[2], s[3]);
    }
    for (int i = t; i < 1152; i += blockDim.x) {
        int q = i & 3, pos = (i >> 2) % 9, o = i / 36;
        int ky = pos / 3, kx = pos % 3;
        int s[4];
        #pragma unroll
        for (int j = 0; j < 4; j++)
            s[j] = sgnf(w3[((o * 16 + (4 * q + j)) * 3 + ky) * 3 + kx]);
        g_w3p[i] = pack4(s[0], s[1], s[2], s[3]);
    }
    for (int i = t; i < 144; i += blockDim.x) {
        int q = i & 7, pos = (i >> 3) % 9, o = i / 72;
        int ky = pos / 3, kx = pos % 3;
        int s[4];
        #pragma unroll
        for (int j = 0; j < 4; j++)
            s[j] = sgnf(w4[((o * 32 + (4 * q + j)) * 3 + ky) * 3 + kx]);
        g_w4p[i] = pack4(s[0], s[1], s[2], s[3]);
    }
}

// ---------------------------------------------------------------------------
// Layer 1: fp conv (3->8), pad 1.0, fused hardtanh+maxpool+sign.
// Block = (b, 2 pooled rows, 128 pooled cols). Input tile staged in smem
// (coalesced, pad applied at load). Math in fma.rn.f32x2: the two x-adjacent
// pool positions per row share one packed FMA.
// ---------------------------------------------------------------------------
__global__ __launch_bounds__(256)
void l1_kernel(const float* __restrict__ x) {
    __shared__ __align__(16) float sx[3][6][260];    // [c][row][col], 258 used
    __shared__ __align__(16) float swd[216 * 2];     // duplicated {w,w} pairs

    int blk = blockIdx.x;
    int pxg = blk & 1;
    int pyg = (blk >> 1) & 127;
    int b   = blk >> 8;
    int px0 = pxg * 128;
    int py0 = pyg * 2;
    int gx0 = 2 * px0 - 1;
    int gy0 = 2 * py0 - 1;

    for (int i = threadIdx.x; i < 216; i += 256) {
        float w = g_w1f[i];
        swd[2 * i] = w; swd[2 * i + 1] = w;
    }
    const int NLOAD = 3 * 6 * 258;
    for (int i = threadIdx.x; i < NLOAD; i += 256) {
        int c   = i / (6 * 258);
        int rem = i % (6 * 258);
        int r   = rem / 258;
        int col = rem % 258;
        int gy = gy0 + r, gx = gx0 + col;
        float v = 1.0f;
        if ((unsigned)gy < 512u && (unsigned)gx < 512u)
            v = x[((size_t)(b * 3 + c) * 512 + gy) * 512 + gx];
        sx[c][r][col] = v;
    }
    __syncthreads();

    int lx = threadIdx.x & 127;
    int ly = threadIdx.x >> 7;
    int cb = 2 * lx;                                  // local col of patch
    int rb = 2 * ly;                                  // local row of patch

    unsigned long long acc01[8], acc23[8];            // (dx0,dx1) at dy=0 / dy=1
    #pragma unroll
    for (int o = 0; o < 8; o++) { acc01[o] = 0ull; acc23[o] = 0ull; }

    #pragma unroll
    for (int c = 0; c < 3; c++) {
        unsigned long long a[4][3];                   // row r, pair start kx
        #pragma unroll
        for (int r = 0; r < 4; r++) {
            float2 v01 = *(const float2*)&sx[c][rb + r][cb];
            float2 v23 = *(const float2*)&sx[c][rb + r][cb + 2];
            a[r][0] = pk2(v01.x, v01.y);
            a[r][1] = pk2(v01.y, v23.x);
            a[r][2] = pk2(v23.x, v23.y);
        }
        #pragma unroll
        for (int ky = 0; ky < 3; ky++)
            #pragma unroll
            for (int kx = 0; kx < 3; kx++)
                #pragma unroll
                for (int o = 0; o < 8; o++) {
                    unsigned long long w2 =
                        *(const unsigned long long*)&swd[2 * (((o * 3 + c) * 3 + ky) * 3 + kx)];
                    acc01[o] = ffma2(a[ky][kx],     w2, acc01[o]);
                    acc23[o] = ffma2(a[ky + 1][kx], w2, acc23[o]);
                }
    }

    int s[8];
    #pragma unroll
    for (int o = 0; o < 8; o++) {
        float f0, f1, f2, f3;
        upk2(acc01[o], f0, f1);
        upk2(acc23[o], f2, f3);
        float m = fmaxf(fmaxf(f0, f1), fmaxf(f2, f3));
        s[o] = sgnf(m);
    }
    uint2 out;
    out.x = (unsigned)pack4(s[0], s[1], s[2], s[3]);
    out.y = (unsigned)pack4(s[4], s[5], s[6], s[7]);
    g_s1[((size_t)b * 256 + (py0 + ly)) * 256 + (px0 + lx)] = out;
}

// ---------------------------------------------------------------------------
// Layer 2: ternary conv (8->16). Block = (b, 2-row group). Thread = one x,
// 2 y rows, all 16 oc. Unchanged from R5.
// ---------------------------------------------------------------------------
__global__ __launch_bounds__(256)
void l2_kernel() {
    __shared__ int sw[288];
    for (int i = threadIdx.x; i < 288; i += blockDim.x) sw[i] = g_w2p[i];
    __syncthreads();
    const int2* sw2 = (const int2*)sw;               // [o*9 + pos]

    int b  = blockIdx.x / 127;
    int y0 = (blockIdx.x % 127) * 2;
    int x  = threadIdx.x;
    if (x >= 254) return;

    int acc[2][16];
    #pragma unroll
    for (int p = 0; p < 2; p++)
        #pragma unroll
        for (int o = 0; o < 16; o++) acc[p][o] = 0;

    #pragma unroll
    for (int cc = 0; cc < 3; cc++) {
        uint2 d[4];                                  // rows y0..y0+3 at col x+cc
        #pragma unroll
        for (int r = 0; r < 4; r++)
            d[r] = g_s1[((size_t)b * 256 + (y0 + r)) * 256 + (x + cc)];
        #pragma unroll
        for (int ky = 0; ky < 3; ky++)
            #pragma unroll
            for (int o = 0; o < 16; o++) {
                int2 w = sw2[o * 9 + ky * 3 + cc];
                #pragma unroll
                for (int p = 0; p < 2; p++) {
                    acc[p][o] = __dp4a((int)d[ky + p].x, w.x, acc[p][o]);
                    acc[p][o] = __dp4a((int)d[ky + p].y, w.y, acc[p][o]);
                }
            }
    }

    #pragma unroll
    for (int p = 0; p < 2; p++) {
        int4 out;
        out.x = pack4(sgni(acc[p][0]),  sgni(acc[p][1]),  sgni(acc[p][2]),  sgni(acc[p][3]));
        out.y = pack4(sgni(acc[p][4]),  sgni(acc[p][5]),  sgni(acc[p][6]),  sgni(acc[p][7]));
        out.z = pack4(sgni(acc[p][8]),  sgni(acc[p][9]),  sgni(acc[p][10]), sgni(acc[p][11]));
        out.w = pack4(sgni(acc[p][12]), sgni(acc[p][13]), sgni(acc[p][14]), sgni(acc[p][15]));
        g_s2[((size_t)b * 254 + (y0 + p)) * 254 + x] = out;
    }
}

// ---------------------------------------------------------------------------
// Layer 3: ternary conv (16->32). Block = (b, 4-row group, og of 8 oc).
// g_s2 tile (6 rows x 254 int4 = 24.4KB) staged in smem once (coalesced);
// single pass over 8 oc with conflict-free LDS.128 reads. Stores uint2 plane.
// ---------------------------------------------------------------------------
__global__ __launch_bounds__(256)
void l3_kernel() {
    __shared__ __align__(16) int4 sd[6][254];
    __shared__ int sw[288];

    int blk = blockIdx.x;
    int og  = blk & 3;
    int yg  = (blk >> 2) % 63;
    int b   = blk / 252;
    int y0  = yg * 4;

    for (int i = threadIdx.x; i < 288; i += 256) sw[i] = g_w3p[og * 288 + i];
    for (int i = threadIdx.x; i < 6 * 254; i += 256) {
        int r = i / 254, c = i % 254;
        sd[r][c] = g_s2[((size_t)b * 254 + (y0 + r)) * 254 + c];
    }
    __syncthreads();

    int x = threadIdx.x;
    if (x < 252) {
        const int4* sw4 = (const int4*)sw;           // [o*9 + pos], o 0..7

        int acc[4][8];
        #pragma unroll
        for (int p = 0; p < 4; p++)
            #pragma unroll
            for (int o = 0; o < 8; o++) acc[p][o] = 0;

        #pragma unroll
        for (int cc = 0; cc < 3; cc++) {
            int4 d[6];
            #pragma unroll
            for (int r = 0; r < 6; r++) d[r] = sd[r][x + cc];
            #pragma unroll
            for (int ky = 0; ky < 3; ky++)
                #pragma unroll
                for (int o = 0; o < 8; o++) {
                    int4 w = sw4[o * 9 + ky * 3 + cc];
                    #pragma unroll
                    for (int p = 0; p < 4; p++) {
                        acc[p][o] = __dp4a(d[ky + p].x, w.x, acc[p][o]);
                        acc[p][o] = __dp4a(d[ky + p].y, w.y, acc[p][o]);
                        acc[p][o] = __dp4a(d[ky + p].z, w.z, acc[p][o]);
                        acc[p][o] = __dp4a(d[ky + p].w, w.w, acc[p][o]);
                    }
                }
        }

        #pragma unroll
        for (int p = 0; p < 4; p++) {
            uint2 v;
            v.x = (unsigned)pack4(sgni(acc[p][0]), sgni(acc[p][1]),
                                  sgni(acc[p][2]), sgni(acc[p][3]));
            v.y = (unsigned)pack4(sgni(acc[p][4]), sgni(acc[p][5]),
                                  sgni(acc[p][6]), sgni(acc[p][7]));
            g_s3v[og][((size_t)b * 252 + (y0 + p)) * 252 + x] = v;
        }
    }
}

// ---------------------------------------------------------------------------
// Layer 4: ternary conv (32->2) + hardtanh -> fp32 out. Block = (b, 2-row
// group). Thread = one x, 2 y rows, both oc. Loads uint2 planes (8ch each).
// ---------------------------------------------------------------------------
__global__ __launch_bounds__(256)
void l4_kernel(float* __restrict__ out) {
    __shared__ int sw[144];
    for (int i = threadIdx.x; i < 144; i += blockDim.x) sw[i] = g_w4p[i];
    __syncthreads();
    const int4* sw4 = (const int4*)sw;               // [(o*9+pos)*2 + half]

    int b  = blockIdx.x / 125;
    int y0 = (blockIdx.x % 125) * 2;
    int x  = threadIdx.x;
    if (x >= 250) return;

    int acc[2][2];
    acc[0][0] = acc[0][1] = acc[1][0] = acc[1][1] = 0;

    #pragma unroll
    for (int cc = 0; cc < 3; cc++) {
        uint2 d[4][4];                               // rows y0..y0+3, 4 planes
        #pragma unroll
        for (int r = 0; r < 4; r++) {
            size_t pix = ((size_t)b * 252 + (y0 + r)) * 252 + (x + cc);
            #pragma unroll
            for (int q = 0; q < 4; q++) d[r][q] = g_s3v[q][pix];
        }
        #pragma unroll
        for (int ky = 0; ky < 3; ky++)
            #pragma unroll
            for (int o = 0; o < 2; o++) {
                int4 wa = sw4[(o * 9 + ky * 3 + cc) * 2 + 0];
                int4 wb = sw4[(o * 9 + ky * 3 + cc) * 2 + 1];
                #pragma unroll
                for (int p = 0; p < 2; p++) {
                    const uint2* dr = d[ky + p];
                    acc[p][o] = __dp4a((int)dr[0].x, wa.x, acc[p][o]);
                    acc[p][o] = __dp4a((int)dr[0].y, wa.y, acc[p][o]);
                    acc[p][o] = __dp4a((int)dr[1].x, wa.z, acc[p][o]);
                    acc[p][o] = __dp4a((int)dr[1].y, wa.w, acc[p][o]);
                    acc[p][o] = __dp4a((int)dr[2].x, wb.x, acc[p][o]);
                    acc[p][o] = __dp4a((int)dr[2].y, wb.y, acc[p][o]);
                    acc[p][o] = __dp4a((int)dr[3].x, wb.z, acc[p][o]);
                    acc[p][o] = __dp4a((int)dr[3].y, wb.w, acc[p][o]);
                }
            }
    }

    #pragma unroll
    for (int p = 0; p < 2; p++)
        #pragma unroll
        for (int o = 0; o < 2; o++) {
            float v = fminf(fmaxf((float)acc[p][o], -1.f), 1.f);
            out[(size_t)b * 125000 + (size_t)o * 62500 + (size_t)(y0 + p) * 250 + x] = v;
        }
}

// ---------------------------------------------------------------------------
extern "C" void kernel_launch(void* const* d_in, const int* in_sizes, int n_in,
                              void* d_out, int out_size) {
    const float* x  = (const float*)d_in[0];
    const float* w1 = (const float*)d_in[1];
    const float* w2 = (const float*)d_in[2];
    const float* w3 = (const float*)d_in[3];
    const float* w4 = (const float*)d_in[4];
    float* out = (float*)d_out;

    prep_kernel<<<1, 256>>>(w1, w2, w3, w4);
    l1_kernel<<<8192, 256>>>(x);                    // block = (b, 2 prow, 128 pcol)
    l2_kernel<<<32 * 127, 256>>>();                 // block = (b, 2 rows)
    l3_kernel<<<32 * 63 * 4, 256>>>();              // block = (b, 4 rows, og)
    l4_kernel<<<32 * 125, 256>>>(out);              // block = (b, 2 rows)
}

// round 8
// speedup vs baseline: 1.3974x; 1.3974x over previous
#include <cuda_runtime.h>
#include <cstdint>

// ---------------------------------------------------------------------------
// MCNET binarized CNN (algebraic identities, see R0):
//   * sign(maxpool(hardtanh(v))) == sign(max(v))
//   * sign(hardtanh(int n)) == sign(n)
//   * L2..L4 activations are ternary {-1,0,+1} int8 sign maps
// R7 = R5 revert + one change: l3 is single-pass over 8 oc with 2 output
// rows per thread (fewer regs -> 4 blocks/SM, fewer redundant loads).
// ---------------------------------------------------------------------------

static __device__ uint2    g_s1[32u * 256 * 256];          // [b,y,x, 8ch]  16.8 MB
static __device__ int4     g_s2[32u * 254 * 254];          // [b,y,x,16ch]  33.0 MB
static __device__ unsigned g_s3u[8][32u * 252 * 252];      // [chgroup][b,y,x] 65 MB

static __device__ float g_w1f[216];    // [o=8][c=3][ky][kx] as float +-1/0
static __device__ int   g_w2p[288];    // [o=16][9 pos][2 packs of 4ch]
static __device__ int   g_w3p[1152];   // [o=32][9 pos][4 packs of 4ch]
static __device__ int   g_w4p[144];    // [o=2 ][9 pos][8 packs of 4ch]

__device__ __forceinline__ int sgnf(float v) { return (v > 0.f) - (v < 0.f); }
__device__ __forceinline__ int sgni(int v)   { return (v > 0) - (v < 0); }
__device__ __forceinline__ int pack4(int a, int b, int c, int d) {
    return (a & 0xFF) | ((b & 0xFF) << 8) | ((c & 0xFF) << 16) | ((d & 0xFF) << 24);
}

// ---------------------------------------------------------------------------
__global__ void prep_kernel(const float* __restrict__ w1, const float* __restrict__ w2,
                            const float* __restrict__ w3, const float* __restrict__ w4) {
    int t = threadIdx.x;
    for (int i = t; i < 216; i += blockDim.x) g_w1f[i] = (float)sgnf(w1[i]);
    for (int i = t; i < 288; i += blockDim.x) {
        int h = i & 1, pos = (i >> 1) % 9, o = i / 18;
        int ky = pos / 3, kx = pos % 3;
        int s[4];
        #pragma unroll
        for (int j = 0; j < 4; j++)
            s[j] = sgnf(w2[((o * 8 + (4 * h + j)) * 3 + ky) * 3 + kx]);
        g_w2p[i] = pack4(s[0], s[1], s[2], s[3]);
    }
    for (int i = t; i < 1152; i += blockDim.x) {
        int q = i & 3, pos = (i >> 2) % 9, o = i / 36;
        int ky = pos / 3, kx = pos % 3;
        int s[4];
        #pragma unroll
        for (int j = 0; j < 4; j++)
            s[j] = sgnf(w3[((o * 16 + (4 * q + j)) * 3 + ky) * 3 + kx]);
        g_w3p[i] = pack4(s[0], s[1], s[2], s[3]);
    }
    for (int i = t; i < 144; i += blockDim.x) {
        int q = i & 7, pos = (i >> 3) % 9, o = i / 72;
        int ky = pos / 3, kx = pos % 3;
        int s[4];
        #pragma unroll
        for (int j = 0; j < 4; j++)
            s[j] = sgnf(w4[((o * 32 + (4 * q + j)) * 3 + ky) * 3 + kx]);
        g_w4p[i] = pack4(s[0], s[1], s[2], s[3]);
    }
}

// ---------------------------------------------------------------------------
// Layer 1: fp conv (3->8), pad 1.0, fused hardtanh+maxpool+sign. (R5 version)
// ---------------------------------------------------------------------------
__global__ __launch_bounds__(256)
void l1_kernel(const float* __restrict__ x) {
    __shared__ float sw[216];
    for (int i = threadIdx.x; i < 216; i += blockDim.x) sw[i] = g_w1f[i];
    __syncthreads();

    int t = blockIdx.x * blockDim.x + threadIdx.x;   // 32*256*256 threads exact
    int px = t & 255;
    int py = (t >> 8) & 255;
    int b  = t >> 16;

    float acc[4][8];
    #pragma unroll
    for (int p = 0; p < 4; p++)
        #pragma unroll
        for (int o = 0; o < 8; o++) acc[p][o] = 0.f;

    int gy0 = 2 * py - 1;
    int gx0 = 2 * px - 1;

    #pragma unroll
    for (int c = 0; c < 3; c++) {
        float p[4][4];
        const float* xc = x + ((size_t)b * 3 + c) * 512 * 512;
        #pragma unroll
        for (int r = 0; r < 4; r++) {
            int gy = gy0 + r;
            bool rok = (unsigned)gy < 512u;
            #pragma unroll
            for (int cc = 0; cc < 4; cc++) {
                int gx = gx0 + cc;
                bool ok = rok && ((unsigned)gx < 512u);
                p[r][cc] = ok ? __ldg(xc + gy * 512 + gx) : 1.0f;
            }
        }
        #pragma unroll
        for (int ky = 0; ky < 3; ky++)
            #pragma unroll
            for (int kx = 0; kx < 3; kx++)
                #pragma unroll
                for (int o = 0; o < 8; o++) {
                    float w = sw[((o * 3 + c) * 3 + ky) * 3 + kx];
                    #pragma unroll
                    for (int dy = 0; dy < 2; dy++)
                        #pragma unroll
                        for (int dx = 0; dx < 2; dx++)
                            acc[dy * 2 + dx][o] = fmaf(p[ky + dy][kx + dx], w,
                                                       acc[dy * 2 + dx][o]);
                }
    }

    int s[8];
    #pragma unroll
    for (int o = 0; o < 8; o++) {
        float m = fmaxf(fmaxf(acc[0][o], acc[1][o]), fmaxf(acc[2][o], acc[3][o]));
        s[o] = sgnf(m);
    }
    uint2 out;
    out.x = (unsigned)pack4(s[0], s[1], s[2], s[3]);
    out.y = (unsigned)pack4(s[4], s[5], s[6], s[7]);
    g_s1[((size_t)b * 256 + py) * 256 + px] = out;
}

// ---------------------------------------------------------------------------
// Layer 2: ternary conv (8->16). Block = (b, 2-row group). Thread = one x,
// 2 y rows, all 16 oc. (R5 version)
// ---------------------------------------------------------------------------
__global__ __launch_bounds__(256)
void l2_kernel() {
    __shared__ int sw[288];
    for (int i = threadIdx.x; i < 288; i += blockDim.x) sw[i] = g_w2p[i];
    __syncthreads();
    const int2* sw2 = (const int2*)sw;               // [o*9 + pos]

    int b  = blockIdx.x / 127;
    int y0 = (blockIdx.x % 127) * 2;
    int x  = threadIdx.x;
    if (x >= 254) return;

    int acc[2][16];
    #pragma unroll
    for (int p = 0; p < 2; p++)
        #pragma unroll
        for (int o = 0; o < 16; o++) acc[p][o] = 0;

    #pragma unroll
    for (int cc = 0; cc < 3; cc++) {
        uint2 d[4];                                  // rows y0..y0+3 at col x+cc
        #pragma unroll
        for (int r = 0; r < 4; r++)
            d[r] = g_s1[((size_t)b * 256 + (y0 + r)) * 256 + (x + cc)];
        #pragma unroll
        for (int ky = 0; ky < 3; ky++)
            #pragma unroll
            for (int o = 0; o < 16; o++) {
                int2 w = sw2[o * 9 + ky * 3 + cc];
                #pragma unroll
                for (int p = 0; p < 2; p++) {
                    acc[p][o] = __dp4a((int)d[ky + p].x, w.x, acc[p][o]);
                    acc[p][o] = __dp4a((int)d[ky + p].y, w.y, acc[p][o]);
                }
            }
    }

    #pragma unroll
    for (int p = 0; p < 2; p++) {
        int4 out;
        out.x = pack4(sgni(acc[p][0]),  sgni(acc[p][1]),  sgni(acc[p][2]),  sgni(acc[p][3]));
        out.y = pack4(sgni(acc[p][4]),  sgni(acc[p][5]),  sgni(acc[p][6]),  sgni(acc[p][7]));
        out.z = pack4(sgni(acc[p][8]),  sgni(acc[p][9]),  sgni(acc[p][10]), sgni(acc[p][11]));
        out.w = pack4(sgni(acc[p][12]), sgni(acc[p][13]), sgni(acc[p][14]), sgni(acc[p][15]));
        g_s2[((size_t)b * 254 + (y0 + p)) * 254 + x] = out;
    }
}

// ---------------------------------------------------------------------------
// Layer 3: ternary conv (16->32). Block = (b, 2-row group, og of 8 oc).
// Thread = one x (coalesced int4 loads), 2 y rows, SINGLE pass over all 8 oc:
// acc 16 regs + d 16 regs -> ~60 regs -> 4 blocks/SM. 12 LDG.128 per thread
// for 576 dp4a (vs R5: 36 for 1152).
// ---------------------------------------------------------------------------
__global__ __launch_bounds__(256)
void l3_kernel() {
    __shared__ int sw[288];                          // weights for this og only
    int blk = blockIdx.x;
    int og  = blk & 3;
    int yg  = (blk >> 2) % 126;
    int b   = blk / 504;                             // 504 = 126*4 blocks per b
    for (int i = threadIdx.x; i < 288; i += blockDim.x) sw[i] = g_w3p[og * 288 + i];
    __syncthreads();
    const int4* sw4 = (const int4*)sw;               // [o*9 + pos], o in 0..7

    int x = threadIdx.x;
    if (x >= 252) return;
    int y0 = yg * 2;

    int acc[2][8];
    #pragma unroll
    for (int p = 0; p < 2; p++)
        #pragma unroll
        for (int o = 0; o < 8; o++) acc[p][o] = 0;

    #pragma unroll
    for (int cc = 0; cc < 3; cc++) {
        int4 d[4];                                   // rows y0..y0+3 at col x+cc
        #pragma unroll
        for (int r = 0; r < 4; r++)
            d[r] = g_s2[((size_t)b * 254 + (y0 + r)) * 254 + (x + cc)];
        #pragma unroll
        for (int ky = 0; ky < 3; ky++)
            #pragma unroll
            for (int o = 0; o < 8; o++) {
                int4 w = sw4[o * 9 + ky * 3 + cc];
                #pragma unroll
                for (int p = 0; p < 2; p++) {
                    acc[p][o] = __dp4a(d[ky + p].x, w.x, acc[p][o]);
                    acc[p][o] = __dp4a(d[ky + p].y, w.y, acc[p][o]);
                    acc[p][o] = __dp4a(d[ky + p].z, w.z, acc[p][o]);
                    acc[p][o] = __dp4a(d[ky + p].w, w.w, acc[p][o]);
                }
            }
    }

    unsigned* plane0 = g_s3u[og * 2 + 0];            // channels og*8 .. og*8+3
    unsigned* plane1 = g_s3u[og * 2 + 1];            // channels og*8+4 .. og*8+7
    #pragma unroll
    for (int p = 0; p < 2; p++) {
        size_t pix = ((size_t)b * 252 + (y0 + p)) * 252 + x;
        plane0[pix] = (unsigned)pack4(sgni(acc[p][0]), sgni(acc[p][1]),
                                      sgni(acc[p][2]), sgni(acc[p][3]));
        plane1[pix] = (unsigned)pack4(sgni(acc[p][4]), sgni(acc[p][5]),
                                      sgni(acc[p][6]), sgni(acc[p][7]));
    }
}

// ---------------------------------------------------------------------------
// Layer 4: ternary conv (32->2) + hardtanh -> fp32 out. Block = (b, 2-row
// group). Thread = one x, 2 y rows, both oc. (R5 version)
// ---------------------------------------------------------------------------
__global__ __launch_bounds__(256)
void l4_kernel(float* __restrict__ out) {
    __shared__ int sw[144];
    for (int i = threadIdx.x; i < 144; i += blockDim.x) sw[i] = g_w4p[i];
    __syncthreads();
    const int4* sw4 = (const int4*)sw;               // [(o*9+pos)*2 + half]

    int b  = blockIdx.x / 125;
    int y0 = (blockIdx.x % 125) * 2;
    int x  = threadIdx.x;
    if (x >= 250) return;

    int acc[2][2];
    acc[0][0] = acc[0][1] = acc[1][0] = acc[1][1] = 0;

    #pragma unroll
    for (int cc = 0; cc < 3; cc++) {
        unsigned d[4][8];                            // rows y0..y0+3, 8 planes
        #pragma unroll
        for (int r = 0; r < 4; r++) {
            size_t pix = ((size_t)b * 252 + (y0 + r)) * 252 + (x + cc);
            #pragma unroll
            for (int q = 0; q < 8; q++) d[r][q] = g_s3u[q][pix];
        }
        #pragma unroll
        for (int ky = 0; ky < 3; ky++)
            #pragma unroll
            for (int o = 0; o < 2; o++) {
                int4 wa = sw4[(o * 9 + ky * 3 + cc) * 2 + 0];
                int4 wb = sw4[(o * 9 + ky * 3 + cc) * 2 + 1];
                #pragma unroll
                for (int p = 0; p < 2; p++) {
                    const unsigned* dr = d[ky + p];
                    acc[p][o] = __dp4a((int)dr[0], wa.x, acc[p][o]);
                    acc[p][o] = __dp4a((int)dr[1], wa.y, acc[p][o]);
                    acc[p][o] = __dp4a((int)dr[2], wa.z, acc[p][o]);
                    acc[p][o] = __dp4a((int)dr[3], wa.w, acc[p][o]);
                    acc[p][o] = __dp4a((int)dr[4], wb.x, acc[p][o]);
                    acc[p][o] = __dp4a((int)dr[5], wb.y, acc[p][o]);
                    acc[p][o] = __dp4a((int)dr[6], wb.z, acc[p][o]);
                    acc[p][o] = __dp4a((int)dr[7], wb.w, acc[p][o]);
                }
            }
    }

    #pragma unroll
    for (int p = 0; p < 2; p++)
        #pragma unroll
        for (int o = 0; o < 2; o++) {
            float v = fminf(fmaxf((float)acc[p][o], -1.f), 1.f);
            out[(size_t)b * 125000 + (size_t)o * 62500 + (size_t)(y0 + p) * 250 + x] = v;
        }
}

// ---------------------------------------------------------------------------
extern "C" void kernel_launch(void* const* d_in, const int* in_sizes, int n_in,
                              void* d_out, int out_size) {
    const float* x  = (const float*)d_in[0];
    const float* w1 = (const float*)d_in[1];
    const float* w2 = (const float*)d_in[2];
    const float* w3 = (const float*)d_in[3];
    const float* w4 = (const float*)d_in[4];
    float* out = (float*)d_out;

    prep_kernel<<<1, 256>>>(w1, w2, w3, w4);
    l1_kernel<<<8192, 256>>>(x);                    // 32*256*256 threads
    l2_kernel<<<32 * 127, 256>>>();                 // block = (b, 2 rows)
    l3_kernel<<<32 * 126 * 4, 256>>>();             // block = (b, 2 rows, og)
    l4_kernel<<<32 * 125, 256>>>(out);              // block = (b, 2 rows)
}

// round 9
// speedup vs baseline: 1.4711x; 1.0527x over previous
#include <cuda_runtime.h>
#include <cstdint>

// ---------------------------------------------------------------------------
// MCNET binarized CNN (algebraic identities, see R0):
//   * sign(maxpool(hardtanh(v))) == sign(max(v))
//   * sign(hardtanh(int n)) == sign(n)
//   * L2..L4 activations are ternary {-1,0,+1} int8 sign maps
// R9: l1 + l3-compute frozen (R7). l2 gets og-split + 4 rows/thread (weight
// LDS per output halved, dp4a:LDS 8:1). g_s3 becomes 4 uint2 planes (8ch)
// so l4 loads LDG.64; l4 does 4 rows/thread.
// ---------------------------------------------------------------------------

static __device__ uint2 g_s1[32u * 256 * 256];         // [b,y,x, 8ch]  16.8 MB
static __device__ int4  g_s2[32u * 254 * 254];         // [b,y,x,16ch]  33.0 MB
static __device__ uint2 g_s3v[4][32u * 252 * 252];     // [plane][b,y,x] 8ch each

static __device__ float g_w1f[216];    // [o=8][c=3][ky][kx] as float +-1/0
static __device__ int   g_w2p[288];    // [o=16][9 pos][2 packs of 4ch]
static __device__ int   g_w3p[1152];   // [o=32][9 pos][4 packs of 4ch]
static __device__ int   g_w4p[144];    // [o=2 ][9 pos][8 packs of 4ch]

__device__ __forceinline__ int sgnf(float v) { return (v > 0.f) - (v < 0.f); }
__device__ __forceinline__ int sgni(int v)   { return (v > 0) - (v < 0); }
__device__ __forceinline__ int pack4(int a, int b, int c, int d) {
    return (a & 0xFF) | ((b & 0xFF) << 8) | ((c & 0xFF) << 16) | ((d & 0xFF) << 24);
}

// ---------------------------------------------------------------------------
__global__ void prep_kernel(const float* __restrict__ w1, const float* __restrict__ w2,
                            const float* __restrict__ w3, const float* __restrict__ w4) {
    int t = threadIdx.x;
    for (int i = t; i < 216; i += blockDim.x) g_w1f[i] = (float)sgnf(w1[i]);
    for (int i = t; i < 288; i += blockDim.x) {
        int h = i & 1, pos = (i >> 1) % 9, o = i / 18;
        int ky = pos / 3, kx = pos % 3;
        int s[4];
        #pragma unroll
        for (int j = 0; j < 4; j++)
            s[j] = sgnf(w2[((o * 8 + (4 * h + j)) * 3 + ky) * 3 + kx]);
        g_w2p[i] = pack4(s[0], s[1], s[2], s[3]);
    }
    for (int i = t; i < 1152; i += blockDim.x) {
        int q = i & 3, pos = (i >> 2) % 9, o = i / 36;
        int ky = pos / 3, kx = pos % 3;
        int s[4];
        #pragma unroll
        for (int j = 0; j < 4; j++)
            s[j] = sgnf(w3[((o * 16 + (4 * q + j)) * 3 + ky) * 3 + kx]);
        g_w3p[i] = pack4(s[0], s[1], s[2], s[3]);
    }
    for (int i = t; i < 144; i += blockDim.x) {
        int q = i & 7, pos = (i >> 3) % 9, o = i / 72;
        int ky = pos / 3, kx = pos % 3;
        int s[4];
        #pragma unroll
        for (int j = 0; j < 4; j++)
            s[j] = sgnf(w4[((o * 32 + (4 * q + j)) * 3 + ky) * 3 + kx]);
        g_w4p[i] = pack4(s[0], s[1], s[2], s[3]);
    }
}

// ---------------------------------------------------------------------------
// Layer 1: fp conv (3->8), pad 1.0, fused hardtanh+maxpool+sign. (frozen)
// ---------------------------------------------------------------------------
__global__ __launch_bounds__(256)
void l1_kernel(const float* __restrict__ x) {
    __shared__ float sw[216];
    for (int i = threadIdx.x; i < 216; i += blockDim.x) sw[i] = g_w1f[i];
    __syncthreads();

    int t = blockIdx.x * blockDim.x + threadIdx.x;   // 32*256*256 threads exact
    int px = t & 255;
    int py = (t >> 8) & 255;
    int b  = t >> 16;

    float acc[4][8];
    #pragma unroll
    for (int p = 0; p < 4; p++)
        #pragma unroll
        for (int o = 0; o < 8; o++) acc[p][o] = 0.f;

    int gy0 = 2 * py - 1;
    int gx0 = 2 * px - 1;

    #pragma unroll
    for (int c = 0; c < 3; c++) {
        float p[4][4];
        const float* xc = x + ((size_t)b * 3 + c) * 512 * 512;
        #pragma unroll
        for (int r = 0; r < 4; r++) {
            int gy = gy0 + r;
            bool rok = (unsigned)gy < 512u;
            #pragma unroll
            for (int cc = 0; cc < 4; cc++) {
                int gx = gx0 + cc;
                bool ok = rok && ((unsigned)gx < 512u);
                p[r][cc] = ok ? __ldg(xc + gy * 512 + gx) : 1.0f;
            }
        }
        #pragma unroll
        for (int ky = 0; ky < 3; ky++)
            #pragma unroll
            for (int kx = 0; kx < 3; kx++)
                #pragma unroll
                for (int o = 0; o < 8; o++) {
                    float w = sw[((o * 3 + c) * 3 + ky) * 3 + kx];
                    #pragma unroll
                    for (int dy = 0; dy < 2; dy++)
                        #pragma unroll
                        for (int dx = 0; dx < 2; dx++)
                            acc[dy * 2 + dx][o] = fmaf(p[ky + dy][kx + dx], w,
                                                       acc[dy * 2 + dx][o]);
                }
    }

    int s[8];
    #pragma unroll
    for (int o = 0; o < 8; o++) {
        float m = fmaxf(fmaxf(acc[0][o], acc[1][o]), fmaxf(acc[2][o], acc[3][o]));
        s[o] = sgnf(m);
    }
    uint2 out;
    out.x = (unsigned)pack4(s[0], s[1], s[2], s[3]);
    out.y = (unsigned)pack4(s[4], s[5], s[6], s[7]);
    g_s1[((size_t)b * 256 + py) * 256 + px] = out;
}

// ---------------------------------------------------------------------------
// Layer 2: ternary conv (8->16). Block = (b, 4-row group, og of 8 oc).
// Thread = one x, up to 4 y rows, 8 oc. dp4a:weight-LDS = 8:1.
// Each og writes its uint2 half of the pixel's int4.
// ---------------------------------------------------------------------------
__global__ __launch_bounds__(256)
void l2_kernel() {
    __shared__ int sw[144];                          // this og's 72 int2
    int blk = blockIdx.x;
    int og  = blk & 1;
    int yg  = (blk >> 1) & 63;
    int b   = blk >> 7;
    for (int i = threadIdx.x; i < 144; i += blockDim.x) sw[i] = g_w2p[og * 144 + i];
    __syncthreads();
    const int2* sw2 = (const int2*)sw;               // [o*9 + pos], o in 0..7

    int x = threadIdx.x;
    if (x >= 254) return;
    int y0 = yg * 4;                                 // outputs y0..y0+3 (<254)

    int acc[4][8];
    #pragma unroll
    for (int p = 0; p < 4; p++)
        #pragma unroll
        for (int o = 0; o < 8; o++) acc[p][o] = 0;

    #pragma unroll
    for (int cc = 0; cc < 3; cc++) {
        uint2 d[6];                                  // input rows y0..y0+5 (clamped)
        #pragma unroll
        for (int r = 0; r < 6; r++) {
            int yi = y0 + r; if (yi > 255) yi = 255;
            d[r] = g_s1[((size_t)b * 256 + yi) * 256 + (x + cc)];
        }
        #pragma unroll
        for (int ky = 0; ky < 3; ky++)
            #pragma unroll
            for (int o = 0; o < 8; o++) {
                int2 w = sw2[o * 9 + ky * 3 + cc];
                #pragma unroll
                for (int p = 0; p < 4; p++) {
                    acc[p][o] = __dp4a((int)d[ky + p].x, w.x, acc[p][o]);
                    acc[p][o] = __dp4a((int)d[ky + p].y, w.y, acc[p][o]);
                }
            }
    }

    uint2* s2h = (uint2*)g_s2;                       // pixel = 2 uint2 halves
    #pragma unroll
    for (int p = 0; p < 4; p++) {
        if (y0 + p < 254) {
            uint2 v;
            v.x = (unsigned)pack4(sgni(acc[p][0]), sgni(acc[p][1]),
                                  sgni(acc[p][2]), sgni(acc[p][3]));
            v.y = (unsigned)pack4(sgni(acc[p][4]), sgni(acc[p][5]),
                                  sgni(acc[p][6]), sgni(acc[p][7]));
            s2h[(((size_t)b * 254 + (y0 + p)) * 254 + x) * 2 + og] = v;
        }
    }
}

// ---------------------------------------------------------------------------
// Layer 3: ternary conv (16->32). Block = (b, 2-row group, og of 8 oc).
// Compute identical to R7; stores one uint2 plane element per row.
// ---------------------------------------------------------------------------
__global__ __launch_bounds__(256)
void l3_kernel() {
    __shared__ int sw[288];                          // weights for this og only
    int blk = blockIdx.x;
    int og  = blk & 3;
    int yg  = (blk >> 2) % 126;
    int b   = blk / 504;                             // 504 = 126*4 blocks per b
    for (int i = threadIdx.x; i < 288; i += blockDim.x) sw[i] = g_w3p[og * 288 + i];
    __syncthreads();
    const int4* sw4 = (const int4*)sw;               // [o*9 + pos], o in 0..7

    int x = threadIdx.x;
    if (x >= 252) return;
    int y0 = yg * 2;

    int acc[2][8];
    #pragma unroll
    for (int p = 0; p < 2; p++)
        #pragma unroll
        for (int o = 0; o < 8; o++) acc[p][o] = 0;

    #pragma unroll
    for (int cc = 0; cc < 3; cc++) {
        int4 d[4];                                   // rows y0..y0+3 at col x+cc
        #pragma unroll
        for (int r = 0; r < 4; r++)
            d[r] = g_s2[((size_t)b * 254 + (y0 + r)) * 254 + (x + cc)];
        #pragma unroll
        for (int ky = 0; ky < 3; ky++)
            #pragma unroll
            for (int o = 0; o < 8; o++) {
                int4 w = sw4[o * 9 + ky * 3 + cc];
                #pragma unroll
                for (int p = 0; p < 2; p++) {
                    acc[p][o] = __dp4a(d[ky + p].x, w.x, acc[p][o]);
                    acc[p][o] = __dp4a(d[ky + p].y, w.y, acc[p][o]);
                    acc[p][o] = __dp4a(d[ky + p].z, w.z, acc[p][o]);
                    acc[p][o] = __dp4a(d[ky + p].w, w.w, acc[p][o]);
                }
            }
    }

    #pragma unroll
    for (int p = 0; p < 2; p++) {
        size_t pix = ((size_t)b * 252 + (y0 + p)) * 252 + x;
        uint2 v;
        v.x = (unsigned)pack4(sgni(acc[p][0]), sgni(acc[p][1]),
                              sgni(acc[p][2]), sgni(acc[p][3]));
        v.y = (unsigned)pack4(sgni(acc[p][4]), sgni(acc[p][5]),
                              sgni(acc[p][6]), sgni(acc[p][7]));
        g_s3v[og][pix] = v;                          // channels og*8 .. og*8+7
    }
}

// ---------------------------------------------------------------------------
// Layer 4: ternary conv (32->2) + hardtanh -> fp32 out. Block = (b, 4-row
// group). Thread = one x, up to 4 y rows, both oc. uint2 plane loads.
// ---------------------------------------------------------------------------
__global__ __launch_bounds__(256)
void l4_kernel(float* __restrict__ out) {
    __shared__ int sw[144];
    for (int i = threadIdx.x; i < 144; i += blockDim.x) sw[i] = g_w4p[i];
    __syncthreads();
    const int4* sw4 = (const int4*)sw;               // [(o*9+pos)*2 + half]

    int b  = blockIdx.x / 63;
    int yg = blockIdx.x % 63;
    int x  = threadIdx.x;
    if (x >= 250) return;
    int y0 = yg * 4;                                 // outputs y0..y0+3 (<250)

    int acc[4][2];
    #pragma unroll
    for (int p = 0; p < 4; p++) { acc[p][0] = 0; acc[p][1] = 0; }

    #pragma unroll
    for (int cc = 0; cc < 3; cc++) {
        uint2 d[6][4];                               // rows y0..y0+5, 4 planes
        #pragma unroll
        for (int r = 0; r < 6; r++) {
            int yi = y0 + r; if (yi > 251) yi = 251;
            size_t pix = ((size_t)b * 252 + yi) * 252 + (x + cc);
            #pragma unroll
            for (int q = 0; q < 4; q++) d[r][q] = g_s3v[q][pix];
        }
        #pragma unroll
        for (int ky = 0; ky < 3; ky++)
            #pragma unroll
            for (int o = 0; o < 2; o++) {
                int4 wa = sw4[(o * 9 + ky * 3 + cc) * 2 + 0];
                int4 wb = sw4[(o * 9 + ky * 3 + cc) * 2 + 1];
                #pragma unroll
                for (int p = 0; p < 4; p++) {
                    const uint2* dr = d[ky + p];
                    acc[p][o] = __dp4a((int)dr[0].x, wa.x, acc[p][o]);
                    acc[p][o] = __dp4a((int)dr[0].y, wa.y, acc[p][o]);
                    acc[p][o] = __dp4a((int)dr[1].x, wa.z, acc[p][o]);
                    acc[p][o] = __dp4a((int)dr[1].y, wa.w, acc[p][o]);
                    acc[p][o] = __dp4a((int)dr[2].x, wb.x, acc[p][o]);
                    acc[p][o] = __dp4a((int)dr[2].y, wb.y, acc[p][o]);
                    acc[p][o] = __dp4a((int)dr[3].x, wb.z, acc[p][o]);
                    acc[p][o] = __dp4a((int)dr[3].y, wb.w, acc[p][o]);
                }
            }
    }

    #pragma unroll
    for (int p = 0; p < 4; p++) {
        if (y0 + p < 250) {
            #pragma unroll
            for (int o = 0; o < 2; o++) {
                float v = fminf(fmaxf((float)acc[p][o], -1.f), 1.f);
                out[(size_t)b * 125000 + (size_t)o * 62500 + (size_t)(y0 + p) * 250 + x] = v;
            }
        }
    }
}

// ---------------------------------------------------------------------------
extern "C" void kernel_launch(void* const* d_in, const int* in_sizes, int n_in,
                              void* d_out, int out_size) {
    const float* x  = (const float*)d_in[0];
    const float* w1 = (const float*)d_in[1];
    const float* w2 = (const float*)d_in[2];
    const float* w3 = (const float*)d_in[3];
    const float* w4 = (const float*)d_in[4];
    float* out = (float*)d_out;

    prep_kernel<<<1, 256>>>(w1, w2, w3, w4);
    l1_kernel<<<8192, 256>>>(x);                    // 32*256*256 threads
    l2_kernel<<<32 * 64 * 2, 256>>>();              // block = (b, 4 rows, og)
    l3_kernel<<<32 * 126 * 4, 256>>>();             // block = (b, 2 rows, og)
    l4_kernel<<<32 * 63, 256>>>(out);               // block = (b, 4 rows)
}